// round 16
// baseline (speedup 1.0000x reference)
#include <cuda_runtime.h>
#include <cuda_fp16.h>
#include <math.h>
#include <float.h>

#define D      256
#define BM     128
#define BN     64
#define NSPLIT 9
#define NTHR   512
#define QSTR   264
#define KSTR   72
#define MAXB   2048
#define MAXROWS 34944

// ---- smem layout (bytes) ----
#define OFF_Q   0                  // 128 x 264 fp16 = 67584
#define OFF_KV  67584              // 2 slots x 9216
#define KVBUF   9216
#define OFF_P   86016              // 128 x 72 fp16 = 18432
#define OFF_FLT 104448             // m 128, l 128, osc 128, redm 512, reds 512 floats
#define SMEM_BYTES 110080

__device__ float g_Opart[(size_t)NSPLIT * MAXB * D];
__device__ float g_m[NSPLIT * MAXB];
__device__ float g_l[NSPLIT * MAXB];
__device__ __half g_K[(size_t)MAXROWS * D];
__device__ __half g_V[(size_t)MAXROWS * D];

__device__ __forceinline__ unsigned pack_h2(float a, float b) {
    __half2 t = __floats2half2_rn(a, b);
    return *reinterpret_cast<unsigned*>(&t);
}
__device__ __forceinline__ void mma_f16(float* c, unsigned a0, unsigned a1,
                                        unsigned a2, unsigned a3,
                                        unsigned b0, unsigned b1) {
    asm volatile(
        "mma.sync.aligned.m16n8k16.row.col.f32.f16.f16.f32 "
        "{%0,%1,%2,%3}, {%4,%5,%6,%7}, {%8,%9}, {%0,%1,%2,%3};\n"
        : "+f"(c[0]), "+f"(c[1]), "+f"(c[2]), "+f"(c[3])
        : "r"(a0), "r"(a1), "r"(a2), "r"(a3), "r"(b0), "r"(b1));
}
__device__ __forceinline__ void ldsm_x4(unsigned& r0, unsigned& r1, unsigned& r2,
                                        unsigned& r3, unsigned a) {
    asm volatile("ldmatrix.sync.aligned.m8n8.x4.shared.b16 {%0,%1,%2,%3}, [%4];"
                 : "=r"(r0), "=r"(r1), "=r"(r2), "=r"(r3) : "r"(a));
}
__device__ __forceinline__ void ldsm_x2(unsigned& r0, unsigned& r1, unsigned a) {
    asm volatile("ldmatrix.sync.aligned.m8n8.x2.shared.b16 {%0,%1}, [%2];"
                 : "=r"(r0), "=r"(r1) : "r"(a));
}
__device__ __forceinline__ void ldsm_x2t(unsigned& r0, unsigned& r1, unsigned a) {
    asm volatile("ldmatrix.sync.aligned.m8n8.x2.trans.shared.b16 {%0,%1}, [%2];"
                 : "=r"(r0), "=r"(r1) : "r"(a));
}
__device__ __forceinline__ void cpa16(unsigned dst, const void* src) {
    asm volatile("cp.async.cg.shared.global [%0], [%1], 16;" :: "r"(dst), "l"(src));
}
#define CP_COMMIT() asm volatile("cp.async.commit_group;")
#define CP_WAIT0()  asm volatile("cp.async.wait_group 0;")

// async copy of one 64-key x 64-dim fp16 chunk into a slot (512 threads, 1 op each)
__device__ __forceinline__ void stage_async(const __half* G, int kb, int dc,
                                            int t, unsigned base) {
    int row = t >> 3;
    int c8  = (t & 7) * 8;
    cpa16(base + (unsigned)((row * KSTR + c8) * 2),
          G + (size_t)(kb + row) * D + dc * 64 + c8);
}

// ---- preconvert: fp32 K/V (cache+fresh concat) -> fp16, zero pad ----
extern "C" __global__ void preconvert(const float* __restrict__ Kc,
                                      const float* __restrict__ Vc,
                                      const float* __restrict__ Kn,
                                      const float* __restrict__ Vn,
                                      const int* __restrict__ old_ptr, int Bq)
{
    int old = *old_ptr;
    int nsz = old + Bq;
    int idx = blockIdx.x * blockDim.x + threadIdx.x;   // one per 4 elems
    int row = idx >> 6;
    int c4  = (idx & 63) * 4;
    if (row >= MAXROWS) return;
    size_t o = (size_t)row * D + c4;
    if (row < nsz) {
        const float* ks = (row < old) ? (Kc + (size_t)row * D)
                                      : (Kn + (size_t)(row - old) * D);
        const float* vs = (row < old) ? (Vc + (size_t)row * D)
                                      : (Vn + (size_t)(row - old) * D);
        float4 kv = *(const float4*)(ks + c4);
        float4 vv = *(const float4*)(vs + c4);
        *(uint2*)&g_K[o] = make_uint2(pack_h2(kv.x, kv.y), pack_h2(kv.z, kv.w));
        *(uint2*)&g_V[o] = make_uint2(pack_h2(vv.x, vv.y), pack_h2(vv.z, vv.w));
    } else if (row < nsz + 64) {
        uint2 z = make_uint2(0u, 0u);
        *(uint2*)&g_K[o] = z; *(uint2*)&g_V[o] = z;
    }
}

extern "C" __global__ void __launch_bounds__(NTHR, 1)
attn_mma(const float* __restrict__ Qg, const int* __restrict__ old_ptr, int Bq)
{
    extern __shared__ char smraw[];
    __half* Qs = (__half*)(smraw + OFF_Q);
    __half* Ps = (__half*)(smraw + OFF_P);
    float* m_s  = (float*)(smraw + OFF_FLT);
    float* l_s  = m_s + 128;
    float* oscs = l_s + 128;
    float* redm = oscs + 128;   // [128][4]
    float* reds = redm + 512;   // [128][4]

    const unsigned smb = (unsigned)__cvta_generic_to_shared(smraw);
    const int t    = threadIdx.x;
    const int lane = t & 31;
    const int w    = t >> 5;       // 0..15
    const int grp  = lane >> 2;
    const int qd   = lane & 3;
    const int mg   = w & 3;        // QK: 32-row group
    const int ng   = w >> 2;       // QK: 16-key group
    const int wh   = w >> 3;       // PV: 64-row half
    const int wd   = w & 7;        // PV: 8-dim group

    const int old = *old_ptr;
    const int nsz = old + Bq;
    const int q0  = blockIdx.x * BM;
    const int split = blockIdx.y;

    const int kmax  = min(nsz, old + q0 + BM);
    const int chunk = ((kmax + NSPLIT * BN - 1) / (NSPLIT * BN)) * BN;
    const int kbeg  = split * chunk;
    const int kend  = min(kbeg + chunk, kmax);

    // stage Q (pre-scaled 1/16) as fp16
    #pragma unroll
    for (int p = 0; p < 16; p++) {
        int idx = t + NTHR * p;            // 8192 float4
        int r   = idx >> 6;
        int c4  = (idx & 63) * 4;
        float4 v = *(const float4*)(Qg + (size_t)(q0 + r) * D + c4);
        *(uint2*)&Qs[r * QSTR + c4] =
            make_uint2(pack_h2(v.x * 0.0625f, v.y * 0.0625f),
                       pack_h2(v.z * 0.0625f, v.w * 0.0625f));
    }
    if (t < 128) { m_s[t] = -FLT_MAX; l_s[t] = 0.f; }

    float Of[4][4][4];
    #pragma unroll
    for (int a = 0; a < 4; a++)
        #pragma unroll
        for (int b = 0; b < 4; b++)
            #pragma unroll
            for (int c = 0; c < 4; c++) Of[a][b][c] = 0.f;

    stage_async(g_K, kbeg, 0, t, smb + OFF_KV);
    CP_COMMIT();

    for (int kb = kbeg; kb < kend; kb += BN) {
        float S[2][2][4];
        #pragma unroll
        for (int mt = 0; mt < 2; mt++)
            #pragma unroll
            for (int nt = 0; nt < 2; nt++)
                #pragma unroll
                for (int i = 0; i < 4; i++) S[mt][nt][i] = 0.f;

        #pragma unroll
        for (int c = 0; c < 8; c++) {
            CP_WAIT0();
            __syncthreads();
            {
                unsigned nb = smb + OFF_KV + ((unsigned)((c + 1) & 1)) * KVBUF;
                if (c < 3)       stage_async(g_K, kb, c + 1, t, nb);
                else if (c == 3) stage_async(g_V, kb, 0, t, nb);
                else if (c < 7)  stage_async(g_V, kb, c - 3, t, nb);
                else if (kb + BN < kend)
                                 stage_async(g_K, kb + BN, 0, t, nb);
            }
            CP_COMMIT();

            const unsigned kvb = smb + OFF_KV + ((unsigned)(c & 1)) * KVBUF;

            if (c < 4) {
                // ---------- S += Q K^T (dim chunk c) ----------
                const int dc = c;
                #pragma unroll
                for (int ks = 0; ks < 4; ks++) {
                    unsigned b0[2], b1[2];
                    #pragma unroll
                    for (int nt = 0; nt < 2; nt++) {
                        int bkey = 16 * ng + 8 * nt + (lane & 7);
                        int bcol = ks * 16 + 8 * ((lane >> 3) & 1);
                        ldsm_x2(b0[nt], b1[nt], kvb + (unsigned)(bkey * KSTR + bcol) * 2u);
                    }
                    #pragma unroll
                    for (int mt = 0; mt < 2; mt++) {
                        int arow = 32 * mg + 16 * mt + (lane & 7) + 8 * ((lane >> 3) & 1);
                        int acol = dc * 64 + ks * 16 + 8 * (lane >> 4);
                        unsigned a0, a1, a2, a3;
                        ldsm_x4(a0, a1, a2, a3,
                                smb + OFF_Q + (unsigned)(arow * QSTR + acol) * 2u);
                        #pragma unroll
                        for (int nt = 0; nt < 2; nt++)
                            mma_f16(S[mt][nt], a0, a1, a2, a3, b0[nt], b1[nt]);
                    }
                }
            } else {
                if (c == 4) {
                    // ---------- online softmax ----------
                    #pragma unroll
                    for (int mt = 0; mt < 2; mt++) {
                        const int R0 = 32 * mg + 16 * mt + grp, R1 = R0 + 8;
                        const int lim0 = old + q0 + R0, lim1 = old + q0 + R1;
                        float mx0 = -FLT_MAX, mx1 = -FLT_MAX;
                        #pragma unroll
                        for (int nt = 0; nt < 2; nt++) {
                            int kcb = kb + 16 * ng + 8 * nt + 2 * qd;
                            mx0 = fmaxf(mx0, fmaxf((kcb     <= lim0) ? S[mt][nt][0] : -FLT_MAX,
                                                   (kcb + 1 <= lim0) ? S[mt][nt][1] : -FLT_MAX));
                            mx1 = fmaxf(mx1, fmaxf((kcb     <= lim1) ? S[mt][nt][2] : -FLT_MAX,
                                                   (kcb + 1 <= lim1) ? S[mt][nt][3] : -FLT_MAX));
                        }
                        mx0 = fmaxf(mx0, __shfl_xor_sync(0xffffffffu, mx0, 1));
                        mx0 = fmaxf(mx0, __shfl_xor_sync(0xffffffffu, mx0, 2));
                        mx1 = fmaxf(mx1, __shfl_xor_sync(0xffffffffu, mx1, 1));
                        mx1 = fmaxf(mx1, __shfl_xor_sync(0xffffffffu, mx1, 2));
                        if (qd == 0) { redm[R0 * 4 + ng] = mx0; redm[R1 * 4 + ng] = mx1; }
                    }
                    __syncthreads();

                    #pragma unroll
                    for (int mt = 0; mt < 2; mt++) {
                        const int R0 = 32 * mg + 16 * mt + grp, R1 = R0 + 8;
                        const int lim0 = old + q0 + R0, lim1 = old + q0 + R1;
                        float mf0 = m_s[R0], mf1 = m_s[R1];
                        #pragma unroll
                        for (int g = 0; g < 4; g++) {
                            mf0 = fmaxf(mf0, redm[R0 * 4 + g]);
                            mf1 = fmaxf(mf1, redm[R1 * 4 + g]);
                        }
                        float sum0 = 0.f, sum1 = 0.f;
                        #pragma unroll
                        for (int nt = 0; nt < 2; nt++) {
                            int kcb = kb + 16 * ng + 8 * nt + 2 * qd;
                            float p0 = (kcb     <= lim0) ? __expf(S[mt][nt][0] - mf0) : 0.f;
                            float p1 = (kcb + 1 <= lim0) ? __expf(S[mt][nt][1] - mf0) : 0.f;
                            float p2 = (kcb     <= lim1) ? __expf(S[mt][nt][2] - mf1) : 0.f;
                            float p3 = (kcb + 1 <= lim1) ? __expf(S[mt][nt][3] - mf1) : 0.f;
                            sum0 += p0 + p1; sum1 += p2 + p3;
                            int kc = 16 * ng + 8 * nt + 2 * qd;
                            *(unsigned*)&Ps[R0 * KSTR + kc] = pack_h2(p0, p1);
                            *(unsigned*)&Ps[R1 * KSTR + kc] = pack_h2(p2, p3);
                        }
                        sum0 += __shfl_xor_sync(0xffffffffu, sum0, 1);
                        sum0 += __shfl_xor_sync(0xffffffffu, sum0, 2);
                        sum1 += __shfl_xor_sync(0xffffffffu, sum1, 1);
                        sum1 += __shfl_xor_sync(0xffffffffu, sum1, 2);
                        if (qd == 0) { reds[R0 * 4 + ng] = sum0; reds[R1 * 4 + ng] = sum1; }
                    }
                    __syncthreads();

                    if (t < 128) {
                        float mo = m_s[t], mf = mo;
                        #pragma unroll
                        for (int g = 0; g < 4; g++) mf = fmaxf(mf, redm[t * 4 + g]);
                        float sc = __expf(mo - mf);
                        l_s[t] = l_s[t] * sc + reds[t * 4] + reds[t * 4 + 1]
                                             + reds[t * 4 + 2] + reds[t * 4 + 3];
                        m_s[t] = mf;
                        oscs[t] = sc;
                    }
                    __syncthreads();

                    #pragma unroll
                    for (int mt2 = 0; mt2 < 4; mt2++) {
                        float sa = oscs[64 * wh + 16 * mt2 + grp];
                        float sb = oscs[64 * wh + 16 * mt2 + grp + 8];
                        #pragma unroll
                        for (int dcx = 0; dcx < 4; dcx++) {
                            Of[dcx][mt2][0] *= sa; Of[dcx][mt2][1] *= sa;
                            Of[dcx][mt2][2] *= sb; Of[dcx][mt2][3] *= sb;
                        }
                    }
                }

                // ---------- O += P V (dim chunk c-4) ----------
                const int dc = c - 4;
                #pragma unroll
                for (int kk = 0; kk < 4; kk++) {
                    int bkey = kk * 16 + (lane & 7) + 8 * ((lane >> 3) & 1);
                    unsigned b0, b1;
                    ldsm_x2t(b0, b1, kvb + (unsigned)(bkey * KSTR + wd * 8) * 2u);
                    #pragma unroll
                    for (int mt2 = 0; mt2 < 4; mt2++) {
                        int arow = 64 * wh + 16 * mt2 + (lane & 7) + 8 * ((lane >> 3) & 1);
                        int acol = kk * 16 + 8 * (lane >> 4);
                        unsigned p0, p1, p2, p3;
                        ldsm_x4(p0, p1, p2, p3,
                                smb + OFF_P + (unsigned)(arow * KSTR + acol) * 2u);
                        mma_f16(Of[dc][mt2], p0, p1, p2, p3, b0, b1);
                    }
                }
            }
        }
    }

    __syncthreads();
    size_t obase = ((size_t)split * MAXB + q0) * D;
    #pragma unroll
    for (int dc = 0; dc < 4; dc++) {
        int d = dc * 64 + wd * 8 + 2 * qd;
        #pragma unroll
        for (int mt2 = 0; mt2 < 4; mt2++) {
            int r = 64 * wh + 16 * mt2 + grp;
            *(float2*)&g_Opart[obase + (size_t)r * D + d] =
                make_float2(Of[dc][mt2][0], Of[dc][mt2][1]);
            *(float2*)&g_Opart[obase + (size_t)(r + 8) * D + d] =
                make_float2(Of[dc][mt2][2], Of[dc][mt2][3]);
        }
    }
    if (t < 128) {
        g_m[split * MAXB + q0 + t] = m_s[t];
        g_l[split * MAXB + q0 + t] = l_s[t];
    }
}

extern "C" __global__ void combine_kernel(float* __restrict__ out, int Bq)
{
    int idx = blockIdx.x * blockDim.x + threadIdx.x;
    if (idx >= Bq * D) return;
    int q = idx / D;
    int vd = idx - q * D;
    float M = -FLT_MAX;
    #pragma unroll
    for (int s = 0; s < NSPLIT; s++) M = fmaxf(M, g_m[s * MAXB + q]);
    float num = 0.f, den = 0.f;
    #pragma unroll
    for (int s = 0; s < NSPLIT; s++) {
        float wv = __expf(g_m[s * MAXB + q] - M);
        den += wv * g_l[s * MAXB + q];
        num += wv * g_Opart[((size_t)s * MAXB + q) * D + vd];
    }
    out[idx] = num / den;
}

extern "C" void kernel_launch(void* const* d_in, const int* in_sizes, int n_in,
                              void* d_out, int out_size)
{
    const float* q  = (const float*)d_in[0];
    const float* k  = (const float*)d_in[1];
    const float* v  = (const float*)d_in[2];
    const float* Kc = (const float*)d_in[3];
    const float* Vc = (const float*)d_in[4];
    const int* oldp = (const int*)d_in[5];
    int Bq      = in_sizes[0] / D;
    int memrows = in_sizes[3] / D;

    int rows = memrows + Bq + 64;
    if (rows > MAXROWS) rows = MAXROWS;
    long total = (long)rows * 64;
    preconvert<<<(unsigned)((total + 255) / 256), 256>>>(Kc, Vc, k, v, oldp, Bq);

    cudaFuncSetAttribute((const void*)attn_mma,
                         cudaFuncAttributeMaxDynamicSharedMemorySize, SMEM_BYTES);
    dim3 grid(Bq / BM, NSPLIT);
    attn_mma<<<grid, NTHR, SMEM_BYTES>>>(q, oldp, Bq);
    combine_kernel<<<(Bq * D + 255) / 256, 256>>>((float*)d_out, Bq);
}